// round 15
// baseline (speedup 1.0000x reference)
#include <cuda_runtime.h>
#include <cuda_bf16.h>
#include <cstdint>

#define NN 100000
#define NE 1600000
#define DIN 128
#define DH  64
#define ELLW 64   // max degree slots per node (Poisson(16) tail: P(>64) ~ e^-40)

// bf16 payloads: 64 bf16 per node = 128 B per row (8 uint4 / 16 uint2).
__device__ __align__(16) unsigned short g_ybf[NN * DH];   // bf16(x @ w1a)
__device__ __align__(16) unsigned short g_t1bf[NN * DH];  // bf16(relu(y+b1a+agg))
__device__ __align__(16) unsigned short g_zbf[NN * DH];   // bf16(h1 @ w2a)
__device__ __align__(16) float g_sums[DH];
__device__ int g_deg[NN];
__device__ int g_ell[NN * ELLW];
__device__ int g_done;

// ---------------------------------------------------------------------------
// bf16 helpers
// ---------------------------------------------------------------------------
__device__ __forceinline__ uint32_t bf2(float a, float b) {
    __nv_bfloat162 h = __float22bfloat162_rn(make_float2(a, b));
    return *(uint32_t*)&h;
}
__device__ __forceinline__ float4 bf16x4_to_f4(uint2 u) {
    __nv_bfloat162 lo = *(__nv_bfloat162*)&u.x;
    __nv_bfloat162 hi = *(__nv_bfloat162*)&u.y;
    float2 a = __bfloat1622float2(lo);
    float2 b = __bfloat1622float2(hi);
    return make_float4(a.x, a.y, b.x, b.y);
}
__device__ __forceinline__ void acc_bf16x8(float* acc, uint4 u) {
    float2 a = __bfloat1622float2(*(__nv_bfloat162*)&u.x);
    float2 b = __bfloat1622float2(*(__nv_bfloat162*)&u.y);
    float2 c = __bfloat1622float2(*(__nv_bfloat162*)&u.z);
    float2 d = __bfloat1622float2(*(__nv_bfloat162*)&u.w);
    acc[0] += a.x; acc[1] += a.y; acc[2] += b.x; acc[3] += b.y;
    acc[4] += c.x; acc[5] += c.y; acc[6] += d.x; acc[7] += d.y;
}

// ---------------------------------------------------------------------------
// ELL fill
// ---------------------------------------------------------------------------
__global__ void fill_ell_kernel(const int* __restrict__ ei) {
    int i = blockIdx.x * blockDim.x + threadIdx.x;
    if (i >= NE / 4) return;
    int4 s4 = ((const int4*)ei)[i];
    int4 d4 = ((const int4*)(ei + NE))[i];
    int ss[4] = {s4.x, s4.y, s4.z, s4.w};
    int dd[4] = {d4.x, d4.y, d4.z, d4.w};
    #pragma unroll
    for (int k = 0; k < 4; k++) {
        unsigned src = (unsigned)ss[k];
        unsigned dst = (unsigned)dd[k];
        if (src >= NN || dst >= NN) continue;
        int slot = atomicAdd(&g_deg[dst], 1);
        if (slot < ELLW) g_ell[dst * ELLW + slot] = (int)src;
    }
}

// ---------------------------------------------------------------------------
// ELL gather core: 8 lanes per node, uint4 payload loads (full 128B row per
// warp-LDG), int4 index loads, 8-deep unroll.
// c = uint4 channel (0..7).  acc = 8 floats.
// ---------------------------------------------------------------------------
__device__ __forceinline__ void gather_row_bf8(const unsigned short* __restrict__ vec,
                                               int base, int d, int c,
                                               float* acc) {
    const uint4* v4 = (const uint4*)vec;   // 8 uint4 per node row
    int e = 0;
    for (; e + 8 <= d; e += 8) {
        int4 i0 = *(const int4*)&g_ell[base + e];
        int4 i1 = *(const int4*)&g_ell[base + e + 4];
        uint4 u0 = v4[(size_t)i0.x * 8 + c];
        uint4 u1 = v4[(size_t)i0.y * 8 + c];
        uint4 u2 = v4[(size_t)i0.z * 8 + c];
        uint4 u3 = v4[(size_t)i0.w * 8 + c];
        uint4 u4 = v4[(size_t)i1.x * 8 + c];
        uint4 u5 = v4[(size_t)i1.y * 8 + c];
        uint4 u6 = v4[(size_t)i1.z * 8 + c];
        uint4 u7 = v4[(size_t)i1.w * 8 + c];
        acc_bf16x8(acc, u0); acc_bf16x8(acc, u1);
        acc_bf16x8(acc, u2); acc_bf16x8(acc, u3);
        acc_bf16x8(acc, u4); acc_bf16x8(acc, u5);
        acc_bf16x8(acc, u6); acc_bf16x8(acc, u7);
    }
    if (e + 4 <= d) {
        int4 i0 = *(const int4*)&g_ell[base + e];
        uint4 u0 = v4[(size_t)i0.x * 8 + c];
        uint4 u1 = v4[(size_t)i0.y * 8 + c];
        uint4 u2 = v4[(size_t)i0.z * 8 + c];
        uint4 u3 = v4[(size_t)i0.w * 8 + c];
        acc_bf16x8(acc, u0); acc_bf16x8(acc, u1);
        acc_bf16x8(acc, u2); acc_bf16x8(acc, u3);
        e += 4;
    }
    for (; e < d; e++) {
        int s = __ldg(&g_ell[base + e]);
        acc_bf16x8(acc, v4[(size_t)s * 8 + c]);
    }
}

// ---------------------------------------------------------------------------
// GEMM1: y = x @ w1a  (plain FMA 4x4)
// ---------------------------------------------------------------------------
__global__ void gemm1_kernel(const float* __restrict__ x,
                             const float* __restrict__ w1a) {
    extern __shared__ float sm[];
    float* ws = sm;                 // 128*64
    float* xs = sm + DIN * DH;      // 64 rows, stride 132

    const int t = threadIdx.x;
    const int nb = blockIdx.x * 64;

    if (blockIdx.x == 0 && t < DH) g_sums[t] = 0.f;

    #pragma unroll
    for (int i = 0; i < (DIN * DH) / 256; i++)
        ws[i * 256 + t] = w1a[i * 256 + t];

    #pragma unroll
    for (int i = 0; i < 8; i++) {
        int flat = i * 256 + t;     // float4 index
        int node = flat >> 5;
        int f4   = flat & 31;
        float4 v = make_float4(0.f, 0.f, 0.f, 0.f);
        if (nb + node < NN)
            v = ((const float4*)x)[(size_t)(nb + node) * 32 + f4];
        *(float4*)&xs[node * 132 + f4 * 4] = v;
    }
    __syncthreads();

    const int ng = t >> 4;   // nodes 4ng..4ng+3
    const int og = t & 15;   // outs  4og..4og+3

    float acc[4][4] = {};
    #pragma unroll 4
    for (int k = 0; k < DIN; k++) {
        float4 w4 = *(const float4*)&ws[k * DH + og * 4];
        #pragma unroll
        for (int j = 0; j < 4; j++) {
            float xv = xs[(ng * 4 + j) * 132 + k];
            acc[j][0] += xv * w4.x;
            acc[j][1] += xv * w4.y;
            acc[j][2] += xv * w4.z;
            acc[j][3] += xv * w4.w;
        }
    }
    #pragma unroll
    for (int j = 0; j < 4; j++) {
        int node = nb + ng * 4 + j;
        if (node < NN) {
            uint2 u;
            u.x = bf2(acc[j][0], acc[j][1]);
            u.y = bf2(acc[j][2], acc[j][3]);
            ((uint2*)g_ybf)[(size_t)node * 16 + og] = u;
        }
    }
}

// ---------------------------------------------------------------------------
// Gather1: t1[i] = relu(y_i + b1a + agg_i).  32 nodes/block x 8 threads.
// ---------------------------------------------------------------------------
__global__ void gather1_kernel(const float* __restrict__ b1a) {
    const int t = threadIdx.x;
    const int node = blockIdx.x * 32 + (t >> 3);
    const int c = t & 7;
    if (node >= NN) return;
    float acc[8];
    {
        float4 s0 = bf16x4_to_f4(((const uint2*)g_ybf)[(size_t)node * 16 + c * 2 + 0]);
        float4 s1 = bf16x4_to_f4(((const uint2*)g_ybf)[(size_t)node * 16 + c * 2 + 1]);
        float4 b0 = ((const float4*)b1a)[c * 2 + 0];
        float4 b1 = ((const float4*)b1a)[c * 2 + 1];
        acc[0] = s0.x + b0.x; acc[1] = s0.y + b0.y;
        acc[2] = s0.z + b0.z; acc[3] = s0.w + b0.w;
        acc[4] = s1.x + b1.x; acc[5] = s1.y + b1.y;
        acc[6] = s1.z + b1.z; acc[7] = s1.w + b1.w;
    }
    int d = g_deg[node]; d = d < ELLW ? d : ELLW;
    gather_row_bf8(g_ybf, node * ELLW, d, c, acc);
    uint4 u;
    u.x = bf2(fmaxf(acc[0], 0.f), fmaxf(acc[1], 0.f));
    u.y = bf2(fmaxf(acc[2], 0.f), fmaxf(acc[3], 0.f));
    u.z = bf2(fmaxf(acc[4], 0.f), fmaxf(acc[5], 0.f));
    u.w = bf2(fmaxf(acc[6], 0.f), fmaxf(acc[7], 0.f));
    ((uint4*)g_t1bf)[(size_t)node * 8 + c] = u;
}

// ---------------------------------------------------------------------------
// Fused middle (plain FMA 4x4):
//   h1 = relu(t1 @ w1b + b1b);  z = h1 @ w2a -> g_zbf
// ---------------------------------------------------------------------------
__global__ void fused_mid_kernel(const float* __restrict__ w1b,
                                 const float* __restrict__ b1b,
                                 const float* __restrict__ w2a) {
    extern __shared__ float sm[];
    float* ws1 = sm;                   // 64*64
    float* ws2 = sm + 4096;            // 64*64
    float* t1s = sm + 8192;            // 64 x stride 68
    float* h1s = t1s + 64 * 68;        // 64 x stride 68
    __shared__ __align__(16) float b1bs[64];

    const int t = threadIdx.x;
    const int nb = blockIdx.x * 64;

    #pragma unroll
    for (int i = 0; i < 16; i++) {
        ws1[i * 256 + t] = w1b[i * 256 + t];
        ws2[i * 256 + t] = w2a[i * 256 + t];
    }
    if (t < 64) b1bs[t] = b1b[t];

    #pragma unroll
    for (int i = 0; i < 4; i++) {
        int flat = i * 256 + t;   // uint2 index in 64x16
        int node = flat >> 4;
        int f4   = flat & 15;
        float4 v = make_float4(0.f, 0.f, 0.f, 0.f);
        if (nb + node < NN)
            v = bf16x4_to_f4(((const uint2*)g_t1bf)[(size_t)(nb + node) * 16 + f4]);
        *(float4*)&t1s[node * 68 + f4 * 4] = v;
    }
    __syncthreads();

    const int ng = t >> 4;
    const int og = t & 15;

    // stage 2: h1 = relu(t1 @ w1b + b1b)
    {
        float acc[4][4] = {};
        #pragma unroll 4
        for (int k = 0; k < DH; k++) {
            float4 w4 = *(const float4*)&ws1[k * DH + og * 4];
            #pragma unroll
            for (int j = 0; j < 4; j++) {
                float xv = t1s[(ng * 4 + j) * 68 + k];
                acc[j][0] += xv * w4.x;
                acc[j][1] += xv * w4.y;
                acc[j][2] += xv * w4.z;
                acc[j][3] += xv * w4.w;
            }
        }
        float4 bb = *(const float4*)&b1bs[og * 4];
        #pragma unroll
        for (int j = 0; j < 4; j++) {
            float4 h;
            h.x = fmaxf(acc[j][0] + bb.x, 0.f);
            h.y = fmaxf(acc[j][1] + bb.y, 0.f);
            h.z = fmaxf(acc[j][2] + bb.z, 0.f);
            h.w = fmaxf(acc[j][3] + bb.w, 0.f);
            *(float4*)&h1s[(ng * 4 + j) * 68 + og * 4] = h;
        }
    }
    __syncthreads();

    // stage 3: z = h1 @ w2a -> g_zbf
    {
        float acc[4][4] = {};
        #pragma unroll 4
        for (int k = 0; k < DH; k++) {
            float4 w4 = *(const float4*)&ws2[k * DH + og * 4];
            #pragma unroll
            for (int j = 0; j < 4; j++) {
                float xv = h1s[(ng * 4 + j) * 68 + k];
                acc[j][0] += xv * w4.x;
                acc[j][1] += xv * w4.y;
                acc[j][2] += xv * w4.z;
                acc[j][3] += xv * w4.w;
            }
        }
        #pragma unroll
        for (int j = 0; j < 4; j++) {
            int node = nb + ng * 4 + j;
            if (node < NN) {
                uint2 u;
                u.x = bf2(acc[j][0], acc[j][1]);
                u.y = bf2(acc[j][2], acc[j][3]);
                ((uint2*)g_zbf)[(size_t)node * 16 + og] = u;
            }
        }
    }
}

// ---------------------------------------------------------------------------
// Gather2 + pool + final: 32 node-slots/block x 8 lanes, grid-strided;
// block reduce; last block does out = sums @ w2b + NN*b2b.
// ---------------------------------------------------------------------------
__global__ void gather2_kernel(const float* __restrict__ b2a,
                               const float* __restrict__ w2b,
                               const float* __restrict__ b2b,
                               float* __restrict__ out) {
    __shared__ __align__(16) float4 sdA[256];
    __shared__ __align__(16) float4 sdB[256];
    __shared__ int s_last;
    const int t = threadIdx.x;
    const int c = t & 7;
    const int slot = t >> 3;   // 0..31
    float4 b0 = ((const float4*)b2a)[c * 2 + 0];
    float4 b1 = ((const float4*)b2a)[c * 2 + 1];
    float pool[8] = {};

    for (int node = blockIdx.x * 32 + slot; node < NN; node += gridDim.x * 32) {
        float acc[8];
        float4 s0 = bf16x4_to_f4(((const uint2*)g_zbf)[(size_t)node * 16 + c * 2 + 0]);
        float4 s1 = bf16x4_to_f4(((const uint2*)g_zbf)[(size_t)node * 16 + c * 2 + 1]);
        acc[0] = s0.x + b0.x; acc[1] = s0.y + b0.y;
        acc[2] = s0.z + b0.z; acc[3] = s0.w + b0.w;
        acc[4] = s1.x + b1.x; acc[5] = s1.y + b1.y;
        acc[6] = s1.z + b1.z; acc[7] = s1.w + b1.w;
        int d = g_deg[node]; d = d < ELLW ? d : ELLW;
        gather_row_bf8(g_zbf, node * ELLW, d, c, acc);
        #pragma unroll
        for (int j = 0; j < 8; j++)
            pool[j] += fmaxf(acc[j], 0.f);
    }
    sdA[t] = make_float4(pool[0], pool[1], pool[2], pool[3]);
    sdB[t] = make_float4(pool[4], pool[5], pool[6], pool[7]);
    __syncthreads();
    if (t < 8) {
        float4 sa = sdA[t], sb = sdB[t];
        #pragma unroll
        for (int i = 1; i < 32; i++) {
            float4 va = sdA[t + i * 8];
            float4 vb = sdB[t + i * 8];
            sa.x += va.x; sa.y += va.y; sa.z += va.z; sa.w += va.w;
            sb.x += vb.x; sb.y += vb.y; sb.z += vb.z; sb.w += vb.w;
        }
        atomicAdd(&g_sums[t * 8 + 0], sa.x);
        atomicAdd(&g_sums[t * 8 + 1], sa.y);
        atomicAdd(&g_sums[t * 8 + 2], sa.z);
        atomicAdd(&g_sums[t * 8 + 3], sa.w);
        atomicAdd(&g_sums[t * 8 + 4], sb.x);
        atomicAdd(&g_sums[t * 8 + 5], sb.y);
        atomicAdd(&g_sums[t * 8 + 6], sb.z);
        atomicAdd(&g_sums[t * 8 + 7], sb.w);
    }
    __syncthreads();
    if (t == 0) {
        __threadfence();
        int ticket = atomicAdd(&g_done, 1);
        s_last = (ticket == (int)gridDim.x - 1) ? 1 : 0;
    }
    __syncthreads();
    if (s_last && t < 64) {
        float acc = (float)NN * b2b[t];
        #pragma unroll 8
        for (int j = 0; j < 64; j++) {
            float sj;
            asm volatile("ld.global.cg.f32 %0, [%1];" : "=f"(sj) : "l"(&g_sums[j]));
            acc += sj * w2b[j * 64 + t];
        }
        out[t] = acc;
    }
}

// ---------------------------------------------------------------------------
extern "C" void kernel_launch(void* const* d_in, const int* in_sizes, int n_in,
                              void* d_out, int out_size) {
    const float* x   = (const float*)d_in[0];
    const int*   ei  = (const int*)d_in[1];   // int32
    const float* w1a = (const float*)d_in[2];
    const float* b1a = (const float*)d_in[3];
    const float* w1b = (const float*)d_in[4];
    const float* b1b = (const float*)d_in[5];
    const float* w2a = (const float*)d_in[6];
    const float* b2a = (const float*)d_in[7];
    const float* w2b = (const float*)d_in[8];
    const float* b2b = (const float*)d_in[9];
    float*       out = (float*)d_out;

    (void)in_sizes; (void)n_in; (void)out_size;

    const int SMEM_G1  = (DIN * DH + 64 * 132) * 4;           // 66560 B
    const int SMEM_MID = (2 * DH * DH + 2 * 64 * 68) * 4;     // 67584 B
    cudaFuncSetAttribute(gemm1_kernel,
                         cudaFuncAttributeMaxDynamicSharedMemorySize, SMEM_G1);
    cudaFuncSetAttribute(fused_mid_kernel,
                         cudaFuncAttributeMaxDynamicSharedMemorySize, SMEM_MID);

    static cudaStream_t s2 = nullptr;
    static cudaEvent_t ev_fork = nullptr, ev_join = nullptr;
    static void* deg_ptr = nullptr;
    static void* done_ptr = nullptr;
    if (s2 == nullptr) {
        cudaStreamCreateWithFlags(&s2, cudaStreamNonBlocking);
        cudaEventCreateWithFlags(&ev_fork, cudaEventDisableTiming);
        cudaEventCreateWithFlags(&ev_join, cudaEventDisableTiming);
        cudaGetSymbolAddress(&deg_ptr, g_deg);
        cudaGetSymbolAddress(&done_ptr, g_done);
    }

    // Fork: ELL build on s2 concurrently with gemm1 on the main stream.
    cudaEventRecord(ev_fork, 0);
    cudaStreamWaitEvent(s2, ev_fork, 0);

    cudaMemsetAsync(deg_ptr, 0, NN * sizeof(int), s2);
    cudaMemsetAsync(done_ptr, 0, sizeof(int), s2);
    fill_ell_kernel<<<(NE / 4 + 255) / 256, 256, 0, s2>>>(ei);
    cudaEventRecord(ev_join, s2);

    gemm1_kernel<<<(NN + 63) / 64, 256, SMEM_G1>>>(x, w1a);

    // Join: everything below needs both g_ybf and the ELL adjacency.
    cudaStreamWaitEvent(0, ev_join, 0);

    gather1_kernel<<<(NN + 31) / 32, 256>>>(b1a);
    fused_mid_kernel<<<(NN + 63) / 64, 256, SMEM_MID>>>(w1b, b1b, w2a);
    gather2_kernel<<<1184, 256>>>(b2a, w2b, b2b, out);
}

// round 16
// speedup vs baseline: 1.0485x; 1.0485x over previous
#include <cuda_runtime.h>
#include <cuda_bf16.h>
#include <cstdint>

#define NN 100000
#define NE 1600000
#define DIN 128
#define DH  64
#define ELLW 64   // max degree slots per node (Poisson(16) tail: P(>64) ~ e^-40)

// bf16 payloads: 64 bf16 per node = 16 uint2 per node row.
__device__ __align__(16) unsigned short g_ybf[NN * DH];   // bf16(x @ w1a)
__device__ __align__(16) unsigned short g_t1bf[NN * DH];  // bf16(relu(y+b1a+agg))
__device__ __align__(16) unsigned short g_zbf[NN * DH];   // bf16(h1 @ w2a)
__device__ __align__(16) float g_sums[DH];
__device__ int g_deg[NN];
__device__ int g_ell[NN * ELLW];
__device__ int g_done;

// ---------------------------------------------------------------------------
// bf16 helpers
// ---------------------------------------------------------------------------
__device__ __forceinline__ uint32_t bf2(float a, float b) {
    __nv_bfloat162 h = __float22bfloat162_rn(make_float2(a, b));
    return *(uint32_t*)&h;
}
__device__ __forceinline__ void acc_bf16x4(float4& acc, uint2 u) {
    __nv_bfloat162 lo = *(__nv_bfloat162*)&u.x;
    __nv_bfloat162 hi = *(__nv_bfloat162*)&u.y;
    float2 a = __bfloat1622float2(lo);
    float2 b = __bfloat1622float2(hi);
    acc.x += a.x; acc.y += a.y; acc.z += b.x; acc.w += b.y;
}
__device__ __forceinline__ float4 bf16x4_to_f4(uint2 u) {
    __nv_bfloat162 lo = *(__nv_bfloat162*)&u.x;
    __nv_bfloat162 hi = *(__nv_bfloat162*)&u.y;
    float2 a = __bfloat1622float2(lo);
    float2 b = __bfloat1622float2(hi);
    return make_float4(a.x, a.y, b.x, b.y);
}

// ---------------------------------------------------------------------------
// ELL fill
// ---------------------------------------------------------------------------
__global__ void fill_ell_kernel(const int* __restrict__ ei) {
    int i = blockIdx.x * blockDim.x + threadIdx.x;
    if (i >= NE / 4) return;
    int4 s4 = ((const int4*)ei)[i];
    int4 d4 = ((const int4*)(ei + NE))[i];
    int ss[4] = {s4.x, s4.y, s4.z, s4.w};
    int dd[4] = {d4.x, d4.y, d4.z, d4.w};
    #pragma unroll
    for (int k = 0; k < 4; k++) {
        unsigned src = (unsigned)ss[k];
        unsigned dst = (unsigned)dd[k];
        if (src >= NN || dst >= NN) continue;
        int slot = atomicAdd(&g_deg[dst], 1);
        if (slot < ELLW) g_ell[dst * ELLW + slot] = (int)src;
    }
}

// ---------------------------------------------------------------------------
// Gather tail (single node, from offset e; e multiple of 4 on entry)
// ---------------------------------------------------------------------------
__device__ __forceinline__ float4 gather_tail(const unsigned short* __restrict__ vec,
                                              int base, int e, int d, int c,
                                              float4 acc) {
    const uint2* v2 = (const uint2*)vec;
    for (; e + 4 <= d; e += 4) {
        int4 i0 = *(const int4*)&g_ell[base + e];
        uint2 u0 = v2[(size_t)i0.x * 16 + c];
        uint2 u1 = v2[(size_t)i0.y * 16 + c];
        uint2 u2 = v2[(size_t)i0.z * 16 + c];
        uint2 u3 = v2[(size_t)i0.w * 16 + c];
        acc_bf16x4(acc, u0); acc_bf16x4(acc, u1);
        acc_bf16x4(acc, u2); acc_bf16x4(acc, u3);
    }
    for (; e < d; e++) {
        int s = __ldg(&g_ell[base + e]);
        acc_bf16x4(acc, v2[(size_t)s * 16 + c]);
    }
    return acc;
}

// ---------------------------------------------------------------------------
// Pair gather: two independent nodes interleaved (8+8 payload loads in
// flight in the main loop), then per-node tails.
// ---------------------------------------------------------------------------
__device__ __forceinline__ void gather_pair(const unsigned short* __restrict__ vec,
                                            int baseA, int dA,
                                            int baseB, int dB,
                                            int c, float4& accA, float4& accB) {
    const uint2* v2 = (const uint2*)vec;
    int dmin = dA < dB ? dA : dB;
    int e = 0;
    for (; e + 8 <= dmin; e += 8) {
        int4 a0 = *(const int4*)&g_ell[baseA + e];
        int4 a1 = *(const int4*)&g_ell[baseA + e + 4];
        int4 b0 = *(const int4*)&g_ell[baseB + e];
        int4 b1 = *(const int4*)&g_ell[baseB + e + 4];
        uint2 ua0 = v2[(size_t)a0.x * 16 + c];
        uint2 ua1 = v2[(size_t)a0.y * 16 + c];
        uint2 ua2 = v2[(size_t)a0.z * 16 + c];
        uint2 ua3 = v2[(size_t)a0.w * 16 + c];
        uint2 ua4 = v2[(size_t)a1.x * 16 + c];
        uint2 ua5 = v2[(size_t)a1.y * 16 + c];
        uint2 ua6 = v2[(size_t)a1.z * 16 + c];
        uint2 ua7 = v2[(size_t)a1.w * 16 + c];
        uint2 ub0 = v2[(size_t)b0.x * 16 + c];
        uint2 ub1 = v2[(size_t)b0.y * 16 + c];
        uint2 ub2 = v2[(size_t)b0.z * 16 + c];
        uint2 ub3 = v2[(size_t)b0.w * 16 + c];
        uint2 ub4 = v2[(size_t)b1.x * 16 + c];
        uint2 ub5 = v2[(size_t)b1.y * 16 + c];
        uint2 ub6 = v2[(size_t)b1.z * 16 + c];
        uint2 ub7 = v2[(size_t)b1.w * 16 + c];
        acc_bf16x4(accA, ua0); acc_bf16x4(accA, ua1);
        acc_bf16x4(accA, ua2); acc_bf16x4(accA, ua3);
        acc_bf16x4(accA, ua4); acc_bf16x4(accA, ua5);
        acc_bf16x4(accA, ua6); acc_bf16x4(accA, ua7);
        acc_bf16x4(accB, ub0); acc_bf16x4(accB, ub1);
        acc_bf16x4(accB, ub2); acc_bf16x4(accB, ub3);
        acc_bf16x4(accB, ub4); acc_bf16x4(accB, ub5);
        acc_bf16x4(accB, ub6); acc_bf16x4(accB, ub7);
    }
    if (e + 4 <= dmin) {
        int4 a0 = *(const int4*)&g_ell[baseA + e];
        int4 b0 = *(const int4*)&g_ell[baseB + e];
        uint2 ua0 = v2[(size_t)a0.x * 16 + c];
        uint2 ua1 = v2[(size_t)a0.y * 16 + c];
        uint2 ua2 = v2[(size_t)a0.z * 16 + c];
        uint2 ua3 = v2[(size_t)a0.w * 16 + c];
        uint2 ub0 = v2[(size_t)b0.x * 16 + c];
        uint2 ub1 = v2[(size_t)b0.y * 16 + c];
        uint2 ub2 = v2[(size_t)b0.z * 16 + c];
        uint2 ub3 = v2[(size_t)b0.w * 16 + c];
        acc_bf16x4(accA, ua0); acc_bf16x4(accA, ua1);
        acc_bf16x4(accA, ua2); acc_bf16x4(accA, ua3);
        acc_bf16x4(accB, ub0); acc_bf16x4(accB, ub1);
        acc_bf16x4(accB, ub2); acc_bf16x4(accB, ub3);
        e += 4;
    }
    accA = gather_tail(vec, baseA, e, dA, c, accA);
    accB = gather_tail(vec, baseB, e, dB, c, accB);
}

// ---------------------------------------------------------------------------
// GEMM1: y = x @ w1a  (plain FMA 4x4, R13-measured)
// ---------------------------------------------------------------------------
__global__ void gemm1_kernel(const float* __restrict__ x,
                             const float* __restrict__ w1a) {
    extern __shared__ float sm[];
    float* ws = sm;                 // 128*64
    float* xs = sm + DIN * DH;      // 64 rows, stride 132

    const int t = threadIdx.x;
    const int nb = blockIdx.x * 64;

    if (blockIdx.x == 0 && t < DH) g_sums[t] = 0.f;

    #pragma unroll
    for (int i = 0; i < (DIN * DH) / 256; i++)
        ws[i * 256 + t] = w1a[i * 256 + t];

    #pragma unroll
    for (int i = 0; i < 8; i++) {
        int flat = i * 256 + t;     // float4 index
        int node = flat >> 5;
        int f4   = flat & 31;
        float4 v = make_float4(0.f, 0.f, 0.f, 0.f);
        if (nb + node < NN)
            v = ((const float4*)x)[(size_t)(nb + node) * 32 + f4];
        *(float4*)&xs[node * 132 + f4 * 4] = v;
    }
    __syncthreads();

    const int ng = t >> 4;   // nodes 4ng..4ng+3
    const int og = t & 15;   // outs  4og..4og+3

    float acc[4][4] = {};
    #pragma unroll 4
    for (int k = 0; k < DIN; k++) {
        float4 w4 = *(const float4*)&ws[k * DH + og * 4];
        #pragma unroll
        for (int j = 0; j < 4; j++) {
            float xv = xs[(ng * 4 + j) * 132 + k];
            acc[j][0] += xv * w4.x;
            acc[j][1] += xv * w4.y;
            acc[j][2] += xv * w4.z;
            acc[j][3] += xv * w4.w;
        }
    }
    #pragma unroll
    for (int j = 0; j < 4; j++) {
        int node = nb + ng * 4 + j;
        if (node < NN) {
            uint2 u;
            u.x = bf2(acc[j][0], acc[j][1]);
            u.y = bf2(acc[j][2], acc[j][3]);
            ((uint2*)g_ybf)[(size_t)node * 16 + og] = u;
        }
    }
}

// ---------------------------------------------------------------------------
// Gather1: t1[i] = relu(y_i + b1a + agg_i).  32 nodes/block, 16 slots x 16
// lanes, 2 nodes per slot (A = nb+slot, B = nb+16+slot).
// ---------------------------------------------------------------------------
__global__ void gather1_kernel(const float* __restrict__ b1a) {
    const int t = threadIdx.x;
    const int slot = t >> 4;
    const int c = t & 15;
    const int nodeA = blockIdx.x * 32 + slot;
    const int nodeB = nodeA + 16;
    if (nodeA >= NN) return;
    const bool hasB = (nodeB < NN);

    float4 bb = ((const float4*)b1a)[c];
    float4 accA = bf16x4_to_f4(((const uint2*)g_ybf)[(size_t)nodeA * 16 + c]);
    accA.x += bb.x; accA.y += bb.y; accA.z += bb.z; accA.w += bb.w;
    float4 accB = make_float4(0.f, 0.f, 0.f, 0.f);
    int dA = g_deg[nodeA]; dA = dA < ELLW ? dA : ELLW;
    int dB = 0;
    if (hasB) {
        accB = bf16x4_to_f4(((const uint2*)g_ybf)[(size_t)nodeB * 16 + c]);
        accB.x += bb.x; accB.y += bb.y; accB.z += bb.z; accB.w += bb.w;
        dB = g_deg[nodeB]; dB = dB < ELLW ? dB : ELLW;
    }
    gather_pair(g_ybf, nodeA * ELLW, dA, nodeB * ELLW, dB, c, accA, accB);

    uint2 uA;
    uA.x = bf2(fmaxf(accA.x, 0.f), fmaxf(accA.y, 0.f));
    uA.y = bf2(fmaxf(accA.z, 0.f), fmaxf(accA.w, 0.f));
    ((uint2*)g_t1bf)[(size_t)nodeA * 16 + c] = uA;
    if (hasB) {
        uint2 uB;
        uB.x = bf2(fmaxf(accB.x, 0.f), fmaxf(accB.y, 0.f));
        uB.y = bf2(fmaxf(accB.z, 0.f), fmaxf(accB.w, 0.f));
        ((uint2*)g_t1bf)[(size_t)nodeB * 16 + c] = uB;
    }
}

// ---------------------------------------------------------------------------
// Fused middle (plain FMA 4x4):
//   h1 = relu(t1 @ w1b + b1b);  z = h1 @ w2a -> g_zbf
// ---------------------------------------------------------------------------
__global__ void fused_mid_kernel(const float* __restrict__ w1b,
                                 const float* __restrict__ b1b,
                                 const float* __restrict__ w2a) {
    extern __shared__ float sm[];
    float* ws1 = sm;                   // 64*64
    float* ws2 = sm + 4096;            // 64*64
    float* t1s = sm + 8192;            // 64 x stride 68
    float* h1s = t1s + 64 * 68;        // 64 x stride 68
    __shared__ __align__(16) float b1bs[64];

    const int t = threadIdx.x;
    const int nb = blockIdx.x * 64;

    #pragma unroll
    for (int i = 0; i < 16; i++) {
        ws1[i * 256 + t] = w1b[i * 256 + t];
        ws2[i * 256 + t] = w2a[i * 256 + t];
    }
    if (t < 64) b1bs[t] = b1b[t];

    #pragma unroll
    for (int i = 0; i < 4; i++) {
        int flat = i * 256 + t;   // uint2 index in 64x16
        int node = flat >> 4;
        int f4   = flat & 15;
        float4 v = make_float4(0.f, 0.f, 0.f, 0.f);
        if (nb + node < NN)
            v = bf16x4_to_f4(((const uint2*)g_t1bf)[(size_t)(nb + node) * 16 + f4]);
        *(float4*)&t1s[node * 68 + f4 * 4] = v;
    }
    __syncthreads();

    const int ng = t >> 4;
    const int og = t & 15;

    // stage 2: h1 = relu(t1 @ w1b + b1b)
    {
        float acc[4][4] = {};
        #pragma unroll 4
        for (int k = 0; k < DH; k++) {
            float4 w4 = *(const float4*)&ws1[k * DH + og * 4];
            #pragma unroll
            for (int j = 0; j < 4; j++) {
                float xv = t1s[(ng * 4 + j) * 68 + k];
                acc[j][0] += xv * w4.x;
                acc[j][1] += xv * w4.y;
                acc[j][2] += xv * w4.z;
                acc[j][3] += xv * w4.w;
            }
        }
        float4 bb = *(const float4*)&b1bs[og * 4];
        #pragma unroll
        for (int j = 0; j < 4; j++) {
            float4 h;
            h.x = fmaxf(acc[j][0] + bb.x, 0.f);
            h.y = fmaxf(acc[j][1] + bb.y, 0.f);
            h.z = fmaxf(acc[j][2] + bb.z, 0.f);
            h.w = fmaxf(acc[j][3] + bb.w, 0.f);
            *(float4*)&h1s[(ng * 4 + j) * 68 + og * 4] = h;
        }
    }
    __syncthreads();

    // stage 3: z = h1 @ w2a -> g_zbf
    {
        float acc[4][4] = {};
        #pragma unroll 4
        for (int k = 0; k < DH; k++) {
            float4 w4 = *(const float4*)&ws2[k * DH + og * 4];
            #pragma unroll
            for (int j = 0; j < 4; j++) {
                float xv = h1s[(ng * 4 + j) * 68 + k];
                acc[j][0] += xv * w4.x;
                acc[j][1] += xv * w4.y;
                acc[j][2] += xv * w4.z;
                acc[j][3] += xv * w4.w;
            }
        }
        #pragma unroll
        for (int j = 0; j < 4; j++) {
            int node = nb + ng * 4 + j;
            if (node < NN) {
                uint2 u;
                u.x = bf2(acc[j][0], acc[j][1]);
                u.y = bf2(acc[j][2], acc[j][3]);
                ((uint2*)g_zbf)[(size_t)node * 16 + og] = u;
            }
        }
    }
}

// ---------------------------------------------------------------------------
// Gather2 + pool + final: grid-strided 32 nodes/block (2 per slot);
// block reduce; last block does out = sums @ w2b + NN*b2b.
// ---------------------------------------------------------------------------
__global__ void gather2_kernel(const float* __restrict__ b2a,
                               const float* __restrict__ w2b,
                               const float* __restrict__ b2b,
                               float* __restrict__ out) {
    __shared__ __align__(16) float4 sd[256];
    __shared__ int s_last;
    const int t = threadIdx.x;
    const int c = t & 15;
    const int slot = t >> 4;
    float4 bb = ((const float4*)b2a)[c];
    float4 pool = make_float4(0.f, 0.f, 0.f, 0.f);

    for (int n0 = blockIdx.x * 32 + slot; n0 < NN; n0 += gridDim.x * 32) {
        const int nodeA = n0;
        const int nodeB = n0 + 16;
        const bool hasB = (nodeB < NN);
        float4 accA = bf16x4_to_f4(((const uint2*)g_zbf)[(size_t)nodeA * 16 + c]);
        accA.x += bb.x; accA.y += bb.y; accA.z += bb.z; accA.w += bb.w;
        float4 accB = make_float4(0.f, 0.f, 0.f, 0.f);
        int dA = g_deg[nodeA]; dA = dA < ELLW ? dA : ELLW;
        int dB = 0;
        if (hasB) {
            accB = bf16x4_to_f4(((const uint2*)g_zbf)[(size_t)nodeB * 16 + c]);
            accB.x += bb.x; accB.y += bb.y; accB.z += bb.z; accB.w += bb.w;
            dB = g_deg[nodeB]; dB = dB < ELLW ? dB : ELLW;
        }
        gather_pair(g_zbf, nodeA * ELLW, dA, nodeB * ELLW, dB, c, accA, accB);
        pool.x += fmaxf(accA.x, 0.f);
        pool.y += fmaxf(accA.y, 0.f);
        pool.z += fmaxf(accA.z, 0.f);
        pool.w += fmaxf(accA.w, 0.f);
        if (hasB) {
            pool.x += fmaxf(accB.x, 0.f);
            pool.y += fmaxf(accB.y, 0.f);
            pool.z += fmaxf(accB.z, 0.f);
            pool.w += fmaxf(accB.w, 0.f);
        }
    }
    sd[t] = pool;
    __syncthreads();
    if (t < 16) {
        float4 s = sd[t];
        #pragma unroll
        for (int i = 1; i < 16; i++) {
            float4 v = sd[t + i * 16];
            s.x += v.x; s.y += v.y; s.z += v.z; s.w += v.w;
        }
        atomicAdd(&g_sums[t * 4 + 0], s.x);
        atomicAdd(&g_sums[t * 4 + 1], s.y);
        atomicAdd(&g_sums[t * 4 + 2], s.z);
        atomicAdd(&g_sums[t * 4 + 3], s.w);
    }
    __syncthreads();
    if (t == 0) {
        __threadfence();
        int ticket = atomicAdd(&g_done, 1);
        s_last = (ticket == (int)gridDim.x - 1) ? 1 : 0;
    }
    __syncthreads();
    if (s_last && t < 64) {
        float acc = (float)NN * b2b[t];
        #pragma unroll 8
        for (int j = 0; j < 64; j++) {
            float sj;
            asm volatile("ld.global.cg.f32 %0, [%1];" : "=f"(sj) : "l"(&g_sums[j]));
            acc += sj * w2b[j * 64 + t];
        }
        out[t] = acc;
    }
}

// ---------------------------------------------------------------------------
extern "C" void kernel_launch(void* const* d_in, const int* in_sizes, int n_in,
                              void* d_out, int out_size) {
    const float* x   = (const float*)d_in[0];
    const int*   ei  = (const int*)d_in[1];   // int32
    const float* w1a = (const float*)d_in[2];
    const float* b1a = (const float*)d_in[3];
    const float* w1b = (const float*)d_in[4];
    const float* b1b = (const float*)d_in[5];
    const float* w2a = (const float*)d_in[6];
    const float* b2a = (const float*)d_in[7];
    const float* w2b = (const float*)d_in[8];
    const float* b2b = (const float*)d_in[9];
    float*       out = (float*)d_out;

    (void)in_sizes; (void)n_in; (void)out_size;

    const int SMEM_G1  = (DIN * DH + 64 * 132) * 4;           // 66560 B
    const int SMEM_MID = (2 * DH * DH + 2 * 64 * 68) * 4;     // 67584 B
    cudaFuncSetAttribute(gemm1_kernel,
                         cudaFuncAttributeMaxDynamicSharedMemorySize, SMEM_G1);
    cudaFuncSetAttribute(fused_mid_kernel,
                         cudaFuncAttributeMaxDynamicSharedMemorySize, SMEM_MID);

    static cudaStream_t s2 = nullptr;
    static cudaEvent_t ev_fork = nullptr, ev_join = nullptr;
    static void* deg_ptr = nullptr;
    static void* done_ptr = nullptr;
    if (s2 == nullptr) {
        cudaStreamCreateWithFlags(&s2, cudaStreamNonBlocking);
        cudaEventCreateWithFlags(&ev_fork, cudaEventDisableTiming);
        cudaEventCreateWithFlags(&ev_join, cudaEventDisableTiming);
        cudaGetSymbolAddress(&deg_ptr, g_deg);
        cudaGetSymbolAddress(&done_ptr, g_done);
    }

    // Fork: ELL build on s2 concurrently with gemm1 on the main stream.
    cudaEventRecord(ev_fork, 0);
    cudaStreamWaitEvent(s2, ev_fork, 0);

    cudaMemsetAsync(deg_ptr, 0, NN * sizeof(int), s2);
    cudaMemsetAsync(done_ptr, 0, sizeof(int), s2);
    fill_ell_kernel<<<(NE / 4 + 255) / 256, 256, 0, s2>>>(ei);
    cudaEventRecord(ev_join, s2);

    gemm1_kernel<<<(NN + 63) / 64, 256, SMEM_G1>>>(x, w1a);

    // Join: everything below needs both g_ybf and the ELL adjacency.
    cudaStreamWaitEvent(0, ev_join, 0);

    gather1_kernel<<<(NN + 31) / 32, 256>>>(b1a);
    fused_mid_kernel<<<(NN + 63) / 64, 256, SMEM_MID>>>(w1b, b1b, w2a);
    gather2_kernel<<<1184, 256>>>(b2a, w2b, b2b, out);
}

// round 17
// speedup vs baseline: 1.0848x; 1.0345x over previous
#include <cuda_runtime.h>
#include <cuda_bf16.h>
#include <cstdint>

#define NN 100000
#define NE 1600000
#define DIN 128
#define DH  64
#define ELLW 64   // max degree slots per node (Poisson(16) tail: P(>64) ~ e^-40)

// bf16 payloads: 64 bf16 per node = 16 uint2 per node row.
__device__ __align__(16) unsigned short g_ybf[NN * DH];   // bf16(x @ w1a)
__device__ __align__(16) unsigned short g_t1bf[NN * DH];  // bf16(relu(y+b1a+agg))
__device__ __align__(16) unsigned short g_zbf[NN * DH];   // bf16(h1 @ w2a)
__device__ __align__(16) float g_sums[DH];
__device__ int g_deg[NN];
__device__ int g_ell[NN * ELLW];
__device__ int g_done;

// ---------------------------------------------------------------------------
// bf16 helpers
// ---------------------------------------------------------------------------
__device__ __forceinline__ uint32_t bf2(float a, float b) {
    __nv_bfloat162 h = __float22bfloat162_rn(make_float2(a, b));
    return *(uint32_t*)&h;
}
__device__ __forceinline__ void acc_bf16x4(float4& acc, uint2 u) {
    __nv_bfloat162 lo = *(__nv_bfloat162*)&u.x;
    __nv_bfloat162 hi = *(__nv_bfloat162*)&u.y;
    float2 a = __bfloat1622float2(lo);
    float2 b = __bfloat1622float2(hi);
    acc.x += a.x; acc.y += a.y; acc.z += b.x; acc.w += b.y;
}
__device__ __forceinline__ float4 bf16x4_to_f4(uint2 u) {
    __nv_bfloat162 lo = *(__nv_bfloat162*)&u.x;
    __nv_bfloat162 hi = *(__nv_bfloat162*)&u.y;
    float2 a = __bfloat1622float2(lo);
    float2 b = __bfloat1622float2(hi);
    return make_float4(a.x, a.y, b.x, b.y);
}

// ---------------------------------------------------------------------------
// ELL fill
// ---------------------------------------------------------------------------
__global__ void fill_ell_kernel(const int* __restrict__ ei) {
    int i = blockIdx.x * blockDim.x + threadIdx.x;
    if (i >= NE / 4) return;
    int4 s4 = ((const int4*)ei)[i];
    int4 d4 = ((const int4*)(ei + NE))[i];
    int ss[4] = {s4.x, s4.y, s4.z, s4.w};
    int dd[4] = {d4.x, d4.y, d4.z, d4.w};
    #pragma unroll
    for (int k = 0; k < 4; k++) {
        unsigned src = (unsigned)ss[k];
        unsigned dst = (unsigned)dd[k];
        if (src >= NN || dst >= NN) continue;
        int slot = atomicAdd(&g_deg[dst], 1);
        if (slot < ELLW) g_ell[dst * ELLW + slot] = (int)src;
    }
}

// ---------------------------------------------------------------------------
// ELL gather core (R13-measured): bf16 payload, int4 index loads, unroll-8.
// ---------------------------------------------------------------------------
__device__ __forceinline__ float4 gather_row_bf(const unsigned short* __restrict__ vec,
                                                int base, int d, int c,
                                                float4 acc) {
    const uint2* v2 = (const uint2*)vec;   // 16 uint2 per node row
    int e = 0;
    for (; e + 8 <= d; e += 8) {
        int4 i0 = *(const int4*)&g_ell[base + e];
        int4 i1 = *(const int4*)&g_ell[base + e + 4];
        uint2 u0 = v2[(size_t)i0.x * 16 + c];
        uint2 u1 = v2[(size_t)i0.y * 16 + c];
        uint2 u2 = v2[(size_t)i0.z * 16 + c];
        uint2 u3 = v2[(size_t)i0.w * 16 + c];
        uint2 u4 = v2[(size_t)i1.x * 16 + c];
        uint2 u5 = v2[(size_t)i1.y * 16 + c];
        uint2 u6 = v2[(size_t)i1.z * 16 + c];
        uint2 u7 = v2[(size_t)i1.w * 16 + c];
        acc_bf16x4(acc, u0); acc_bf16x4(acc, u1);
        acc_bf16x4(acc, u2); acc_bf16x4(acc, u3);
        acc_bf16x4(acc, u4); acc_bf16x4(acc, u5);
        acc_bf16x4(acc, u6); acc_bf16x4(acc, u7);
    }
    if (e + 4 <= d) {
        int4 i0 = *(const int4*)&g_ell[base + e];
        uint2 u0 = v2[(size_t)i0.x * 16 + c];
        uint2 u1 = v2[(size_t)i0.y * 16 + c];
        uint2 u2 = v2[(size_t)i0.z * 16 + c];
        uint2 u3 = v2[(size_t)i0.w * 16 + c];
        acc_bf16x4(acc, u0); acc_bf16x4(acc, u1);
        acc_bf16x4(acc, u2); acc_bf16x4(acc, u3);
        e += 4;
    }
    for (; e < d; e++) {
        int s = __ldg(&g_ell[base + e]);
        acc_bf16x4(acc, v2[(size_t)s * 16 + c]);
    }
    return acc;
}

// ---------------------------------------------------------------------------
// GEMM1: y = x @ w1a  (plain FMA 4x4, R13-measured)
// ---------------------------------------------------------------------------
__global__ void gemm1_kernel(const float* __restrict__ x,
                             const float* __restrict__ w1a) {
    extern __shared__ float sm[];
    float* ws = sm;                 // 128*64
    float* xs = sm + DIN * DH;      // 64 rows, stride 132

    const int t = threadIdx.x;
    const int nb = blockIdx.x * 64;

    if (blockIdx.x == 0 && t < DH) g_sums[t] = 0.f;

    #pragma unroll
    for (int i = 0; i < (DIN * DH) / 256; i++)
        ws[i * 256 + t] = w1a[i * 256 + t];

    #pragma unroll
    for (int i = 0; i < 8; i++) {
        int flat = i * 256 + t;     // float4 index
        int node = flat >> 5;
        int f4   = flat & 31;
        float4 v = make_float4(0.f, 0.f, 0.f, 0.f);
        if (nb + node < NN)
            v = ((const float4*)x)[(size_t)(nb + node) * 32 + f4];
        *(float4*)&xs[node * 132 + f4 * 4] = v;
    }
    __syncthreads();

    const int ng = t >> 4;   // nodes 4ng..4ng+3
    const int og = t & 15;   // outs  4og..4og+3

    float acc[4][4] = {};
    #pragma unroll 4
    for (int k = 0; k < DIN; k++) {
        float4 w4 = *(const float4*)&ws[k * DH + og * 4];
        #pragma unroll
        for (int j = 0; j < 4; j++) {
            float xv = xs[(ng * 4 + j) * 132 + k];
            acc[j][0] += xv * w4.x;
            acc[j][1] += xv * w4.y;
            acc[j][2] += xv * w4.z;
            acc[j][3] += xv * w4.w;
        }
    }
    #pragma unroll
    for (int j = 0; j < 4; j++) {
        int node = nb + ng * 4 + j;
        if (node < NN) {
            uint2 u;
            u.x = bf2(acc[j][0], acc[j][1]);
            u.y = bf2(acc[j][2], acc[j][3]);
            ((uint2*)g_ybf)[(size_t)node * 16 + og] = u;
        }
    }
}

// ---------------------------------------------------------------------------
// Gather1: t1[i] = relu(y_i + b1a + agg_i).  16 nodes/block x 16 threads.
// ---------------------------------------------------------------------------
__global__ void gather1_kernel(const float* __restrict__ b1a) {
    const int t = threadIdx.x;
    const int node = blockIdx.x * 16 + (t >> 4);
    const int c = t & 15;
    if (node >= NN) return;
    float4 acc = bf16x4_to_f4(((const uint2*)g_ybf)[(size_t)node * 16 + c]);
    float4 bb = ((const float4*)b1a)[c];
    acc.x += bb.x; acc.y += bb.y; acc.z += bb.z; acc.w += bb.w;
    int d = g_deg[node]; d = d < ELLW ? d : ELLW;
    acc = gather_row_bf(g_ybf, node * ELLW, d, c, acc);
    acc.x = fmaxf(acc.x, 0.f); acc.y = fmaxf(acc.y, 0.f);
    acc.z = fmaxf(acc.z, 0.f); acc.w = fmaxf(acc.w, 0.f);
    uint2 u; u.x = bf2(acc.x, acc.y); u.y = bf2(acc.z, acc.w);
    ((uint2*)g_t1bf)[(size_t)node * 16 + c] = u;
}

// ---------------------------------------------------------------------------
// Fused middle (plain FMA 4x4, single reused tile -> 49KB smem, 4 CTAs/SM):
//   stage2: acc = t1 @ w1b  (t1 in smem tile ts)
//   sync; ts overwritten with h1 = relu(acc + b1b); sync
//   stage3: z = h1 @ w2a -> g_zbf
// ---------------------------------------------------------------------------
__global__ void fused_mid_kernel(const float* __restrict__ w1b,
                                 const float* __restrict__ b1b,
                                 const float* __restrict__ w2a) {
    extern __shared__ float sm[];
    float* ws1 = sm;                   // 64*64
    float* ws2 = sm + 4096;            // 64*64
    float* ts  = sm + 8192;            // 64 x stride 68 (t1, then h1)
    __shared__ __align__(16) float b1bs[64];

    const int t = threadIdx.x;
    const int nb = blockIdx.x * 64;

    #pragma unroll
    for (int i = 0; i < 16; i++) {
        ws1[i * 256 + t] = w1b[i * 256 + t];
        ws2[i * 256 + t] = w2a[i * 256 + t];
    }
    if (t < 64) b1bs[t] = b1b[t];

    #pragma unroll
    for (int i = 0; i < 4; i++) {
        int flat = i * 256 + t;   // uint2 index in 64x16
        int node = flat >> 4;
        int f4   = flat & 15;
        float4 v = make_float4(0.f, 0.f, 0.f, 0.f);
        if (nb + node < NN)
            v = bf16x4_to_f4(((const uint2*)g_t1bf)[(size_t)(nb + node) * 16 + f4]);
        *(float4*)&ts[node * 68 + f4 * 4] = v;
    }
    __syncthreads();

    const int ng = t >> 4;
    const int og = t & 15;

    // stage 2: acc = t1 @ w1b (results stay in registers)
    float acc[4][4] = {};
    #pragma unroll 4
    for (int k = 0; k < DH; k++) {
        float4 w4 = *(const float4*)&ws1[k * DH + og * 4];
        #pragma unroll
        for (int j = 0; j < 4; j++) {
            float xv = ts[(ng * 4 + j) * 68 + k];
            acc[j][0] += xv * w4.x;
            acc[j][1] += xv * w4.y;
            acc[j][2] += xv * w4.z;
            acc[j][3] += xv * w4.w;
        }
    }
    __syncthreads();   // all t1 reads complete before overwrite

    {
        float4 bb = *(const float4*)&b1bs[og * 4];
        #pragma unroll
        for (int j = 0; j < 4; j++) {
            float4 h;
            h.x = fmaxf(acc[j][0] + bb.x, 0.f);
            h.y = fmaxf(acc[j][1] + bb.y, 0.f);
            h.z = fmaxf(acc[j][2] + bb.z, 0.f);
            h.w = fmaxf(acc[j][3] + bb.w, 0.f);
            *(float4*)&ts[(ng * 4 + j) * 68 + og * 4] = h;
        }
    }
    __syncthreads();

    // stage 3: z = h1 @ w2a -> g_zbf
    {
        float a2[4][4] = {};
        #pragma unroll 4
        for (int k = 0; k < DH; k++) {
            float4 w4 = *(const float4*)&ws2[k * DH + og * 4];
            #pragma unroll
            for (int j = 0; j < 4; j++) {
                float xv = ts[(ng * 4 + j) * 68 + k];
                a2[j][0] += xv * w4.x;
                a2[j][1] += xv * w4.y;
                a2[j][2] += xv * w4.z;
                a2[j][3] += xv * w4.w;
            }
        }
        #pragma unroll
        for (int j = 0; j < 4; j++) {
            int node = nb + ng * 4 + j;
            if (node < NN) {
                uint2 u;
                u.x = bf2(a2[j][0], a2[j][1]);
                u.y = bf2(a2[j][2], a2[j][3]);
                ((uint2*)g_zbf)[(size_t)node * 16 + og] = u;
            }
        }
    }
}

// ---------------------------------------------------------------------------
// Gather2 + pool + final (R13-measured form)
// ---------------------------------------------------------------------------
__global__ void gather2_kernel(const float* __restrict__ b2a,
                               const float* __restrict__ w2b,
                               const float* __restrict__ b2b,
                               float* __restrict__ out) {
    __shared__ __align__(16) float4 sd[256];
    __shared__ int s_last;
    const int t = threadIdx.x;
    const int c = t & 15;
    const int slot = t >> 4;
    float4 bb = ((const float4*)b2a)[c];
    float4 pool = make_float4(0.f, 0.f, 0.f, 0.f);

    for (int node = blockIdx.x * 16 + slot; node < NN; node += gridDim.x * 16) {
        float4 acc = bf16x4_to_f4(((const uint2*)g_zbf)[(size_t)node * 16 + c]);
        acc.x += bb.x; acc.y += bb.y; acc.z += bb.z; acc.w += bb.w;
        int d = g_deg[node]; d = d < ELLW ? d : ELLW;
        acc = gather_row_bf(g_zbf, node * ELLW, d, c, acc);
        pool.x += fmaxf(acc.x, 0.f);
        pool.y += fmaxf(acc.y, 0.f);
        pool.z += fmaxf(acc.z, 0.f);
        pool.w += fmaxf(acc.w, 0.f);
    }
    sd[t] = pool;
    __syncthreads();
    if (t < 16) {
        float4 s = sd[t];
        #pragma unroll
        for (int i = 1; i < 16; i++) {
            float4 v = sd[t + i * 16];
            s.x += v.x; s.y += v.y; s.z += v.z; s.w += v.w;
        }
        atomicAdd(&g_sums[t * 4 + 0], s.x);
        atomicAdd(&g_sums[t * 4 + 1], s.y);
        atomicAdd(&g_sums[t * 4 + 2], s.z);
        atomicAdd(&g_sums[t * 4 + 3], s.w);
    }
    __syncthreads();
    if (t == 0) {
        __threadfence();
        int ticket = atomicAdd(&g_done, 1);
        s_last = (ticket == (int)gridDim.x - 1) ? 1 : 0;
    }
    __syncthreads();
    if (s_last && t < 64) {
        float acc = (float)NN * b2b[t];
        #pragma unroll 8
        for (int j = 0; j < 64; j++) {
            float sj;
            asm volatile("ld.global.cg.f32 %0, [%1];" : "=f"(sj) : "l"(&g_sums[j]));
            acc += sj * w2b[j * 64 + t];
        }
        out[t] = acc;
    }
}

// ---------------------------------------------------------------------------
extern "C" void kernel_launch(void* const* d_in, const int* in_sizes, int n_in,
                              void* d_out, int out_size) {
    const float* x   = (const float*)d_in[0];
    const int*   ei  = (const int*)d_in[1];   // int32
    const float* w1a = (const float*)d_in[2];
    const float* b1a = (const float*)d_in[3];
    const float* w1b = (const float*)d_in[4];
    const float* b1b = (const float*)d_in[5];
    const float* w2a = (const float*)d_in[6];
    const float* b2a = (const float*)d_in[7];
    const float* w2b = (const float*)d_in[8];
    const float* b2b = (const float*)d_in[9];
    float*       out = (float*)d_out;

    (void)in_sizes; (void)n_in; (void)out_size;

    const int SMEM_G1  = (DIN * DH + 64 * 132) * 4;            // 66560 B
    const int SMEM_MID = (2 * DH * DH + 64 * 68) * 4;          // 50176 B
    cudaFuncSetAttribute(gemm1_kernel,
                         cudaFuncAttributeMaxDynamicSharedMemorySize, SMEM_G1);
    cudaFuncSetAttribute(fused_mid_kernel,
                         cudaFuncAttributeMaxDynamicSharedMemorySize, SMEM_MID);

    static cudaStream_t s2 = nullptr;
    static cudaEvent_t ev_fork = nullptr, ev_join = nullptr;
    static void* deg_ptr = nullptr;
    static void* done_ptr = nullptr;
    if (s2 == nullptr) {
        cudaStreamCreateWithFlags(&s2, cudaStreamNonBlocking);
        cudaEventCreateWithFlags(&ev_fork, cudaEventDisableTiming);
        cudaEventCreateWithFlags(&ev_join, cudaEventDisableTiming);
        cudaGetSymbolAddress(&deg_ptr, g_deg);
        cudaGetSymbolAddress(&done_ptr, g_done);
    }

    // Fork: ELL build on s2 concurrently with gemm1 on the main stream.
    cudaEventRecord(ev_fork, 0);
    cudaStreamWaitEvent(s2, ev_fork, 0);

    cudaMemsetAsync(deg_ptr, 0, NN * sizeof(int), s2);
    cudaMemsetAsync(done_ptr, 0, sizeof(int), s2);
    fill_ell_kernel<<<(NE / 4 + 255) / 256, 256, 0, s2>>>(ei);
    cudaEventRecord(ev_join, s2);

    gemm1_kernel<<<(NN + 63) / 64, 256, SMEM_G1>>>(x, w1a);

    // Join: everything below needs both g_ybf and the ELL adjacency.
    cudaStreamWaitEvent(0, ev_join, 0);

    gather1_kernel<<<(NN + 15) / 16, 256>>>(b1a);
    fused_mid_kernel<<<(NN + 63) / 64, 256, SMEM_MID>>>(w1b, b1b, w2a);
    gather2_kernel<<<1184, 256>>>(b2a, w2b, b2b, out);
}